// round 2
// baseline (speedup 1.0000x reference)
#include <cuda_runtime.h>
#include <cuda_fp16.h>

// CustomAttention: out[b,n] = b0 * sum_m tanh(a0*x[b,n]*x[b,m]) * x[b,m]
// B=16, N=4096. MUFU-bound -> halve MUFU ops with tanh.approx.f16x2.
// Args + tanh in f16 (packed pairs); accumulation in f32 (FFMA vs f32 x_m)
// to keep the 4096-term sums full precision.

#define NBATCH 16
#define NDIM   4096
#define BT     64

__device__ __forceinline__ __half2 tanh2(__half2 v) {
    unsigned u = *reinterpret_cast<unsigned*>(&v);
    unsigned r;
    asm("tanh.approx.f16x2 %0, %1;" : "=r"(r) : "r"(u));
    return *reinterpret_cast<__half2*>(&r);
}

__global__ __launch_bounds__(BT)
void custom_attention_kernel(const float* __restrict__ x,
                             const float* __restrict__ a,
                             const float* __restrict__ b,
                             float* __restrict__ out)
{
    __shared__ float   xs[NDIM];        // f32 row, 16 KB (FFMA weights)
    __shared__ __half2 xh[NDIM / 2];    // f16 pairs, 8 KB (tanh args)

    const int batch = blockIdx.y;
    const float4* __restrict__ xb4 =
        reinterpret_cast<const float4*>(x + batch * NDIM);
    float4* xs4 = reinterpret_cast<float4*>(xs);

    #pragma unroll
    for (int i = threadIdx.x; i < NDIM / 4; i += BT) {
        float4 v = xb4[i];
        xs4[i] = v;
        xh[2 * i]     = __floats2half2_rn(v.x, v.y);
        xh[2 * i + 1] = __floats2half2_rn(v.z, v.w);
    }
    __syncthreads();

    const int n  = blockIdx.x * BT + threadIdx.x;
    const float xn = xs[n];
    const float c  = a[0] * xn;
    const __half2 ch = __float2half2_rn(c);

    const uint4*  __restrict__ xh4 = reinterpret_cast<const uint4*>(xh);  // 512 x (4 half2)
    const float4* __restrict__ s4  = reinterpret_cast<const float4*>(xs); // 1024 x (4 f32)

    float acc0 = 0.f, acc1 = 0.f, acc2 = 0.f, acc3 = 0.f;

    #pragma unroll 4
    for (int j = 0; j < NDIM / 8; ++j) {
        uint4  hv = xh4[j];          // 8 halves (args source)
        float4 v0 = s4[2 * j];       // 8 f32 weights
        float4 v1 = s4[2 * j + 1];

        __half2 h0 = *reinterpret_cast<__half2*>(&hv.x);
        __half2 h1 = *reinterpret_cast<__half2*>(&hv.y);
        __half2 h2 = *reinterpret_cast<__half2*>(&hv.z);
        __half2 h3 = *reinterpret_cast<__half2*>(&hv.w);

        float2 t0 = __half22float2(tanh2(__hmul2(ch, h0)));
        float2 t1 = __half22float2(tanh2(__hmul2(ch, h1)));
        float2 t2 = __half22float2(tanh2(__hmul2(ch, h2)));
        float2 t3 = __half22float2(tanh2(__hmul2(ch, h3)));

        acc0 = fmaf(t0.x, v0.x, acc0);
        acc1 = fmaf(t0.y, v0.y, acc1);
        acc2 = fmaf(t1.x, v0.z, acc2);
        acc3 = fmaf(t1.y, v0.w, acc3);
        acc0 = fmaf(t2.x, v1.x, acc0);
        acc1 = fmaf(t2.y, v1.y, acc1);
        acc2 = fmaf(t3.x, v1.z, acc2);
        acc3 = fmaf(t3.y, v1.w, acc3);
    }

    out[batch * NDIM + n] = b[0] * ((acc0 + acc1) + (acc2 + acc3));
}

extern "C" void kernel_launch(void* const* d_in, const int* in_sizes, int n_in,
                              void* d_out, int out_size)
{
    const float* x = (const float*)d_in[0];
    const float* a = (const float*)d_in[1];
    const float* b = (const float*)d_in[2];
    float* out = (float*)d_out;

    dim3 grid(NDIM / BT, NBATCH);   // 64 x 16 = 1024 blocks
    custom_attention_kernel<<<grid, BT>>>(x, a, b, out);
}

// round 3
// speedup vs baseline: 1.2182x; 1.2182x over previous
#include <cuda_runtime.h>
#include <cuda_fp16.h>

// CustomAttention: out[b,n] = b0 * sum_m tanh(a0*x[b,n]*x[b,m]) * x[b,m]
// B=16, N=4096.
// XU-pipe bound: tanh.approx.f16x2 halves MUFU; chunked half2 accumulation
// (HFMA2, fma pipe) eliminates the F2F stream that shared the XU pipe in R2.
// Split-m x4 per output raises warp count 2048 -> 8192 for latency hiding.

#define NBATCH 16
#define NDIM   4096
#define BT     256          // threads/block: 64 outputs x 4 m-groups
#define OUTS   64           // outputs per block
#define JPT    128          // uint4 (8-elem) loads per thread (1024 elems)
#define CHUNK  16           // j-iterations per fp16 accumulation chunk

__device__ __forceinline__ __half2 tanh2(__half2 v) {
    unsigned u = *reinterpret_cast<unsigned*>(&v);
    unsigned r;
    asm("tanh.approx.f16x2 %0, %1;" : "=r"(r) : "r"(u));
    return *reinterpret_cast<__half2*>(&r);
}

__global__ __launch_bounds__(BT)
void custom_attention_kernel(const float* __restrict__ x,
                             const float* __restrict__ a,
                             const float* __restrict__ b,
                             float* __restrict__ out)
{
    __shared__ __half2 xh[NDIM / 2];   // row in fp16 pairs, 8 KB
    __shared__ float   partial[BT];    // cross-group reduction, 1 KB

    const int batch = blockIdx.y;
    const float* __restrict__ xb = x + batch * NDIM;

    // Cooperative load + f32->f16 convert of the batch row
    const float4* __restrict__ xb4 = reinterpret_cast<const float4*>(xb);
    #pragma unroll
    for (int i = threadIdx.x; i < NDIM / 4; i += BT) {
        float4 v = xb4[i];
        xh[2 * i]     = __floats2half2_rn(v.x, v.y);
        xh[2 * i + 1] = __floats2half2_rn(v.z, v.w);
    }
    __syncthreads();

    const int lane_out = threadIdx.x & (OUTS - 1);  // which output in block
    const int grp      = threadIdx.x >> 6;          // which m quarter (0..3)
    const int n        = blockIdx.x * OUTS + lane_out;

    const float   c  = a[0] * xb[n];                // f32-exact scale
    const __half2 ch = __float2half2_rn(c);

    const uint4* __restrict__ xh4 = reinterpret_cast<const uint4*>(xh);
    const int jbase = grp * JPT;                    // this thread's m quarter

    float facc = 0.f;

    #pragma unroll 1
    for (int chunk = 0; chunk < JPT / CHUNK; ++chunk) {
        __half2 acc0 = __float2half2_rn(0.f);
        __half2 acc1 = __float2half2_rn(0.f);
        __half2 acc2 = __float2half2_rn(0.f);
        __half2 acc3 = __float2half2_rn(0.f);

        #pragma unroll
        for (int jj = 0; jj < CHUNK; ++jj) {
            uint4 hv = xh4[jbase + chunk * CHUNK + jj];   // 8 halves, LDS broadcast
            __half2 h0 = *reinterpret_cast<__half2*>(&hv.x);
            __half2 h1 = *reinterpret_cast<__half2*>(&hv.y);
            __half2 h2 = *reinterpret_cast<__half2*>(&hv.z);
            __half2 h3 = *reinterpret_cast<__half2*>(&hv.w);

            acc0 = __hfma2(tanh2(__hmul2(ch, h0)), h0, acc0);
            acc1 = __hfma2(tanh2(__hmul2(ch, h1)), h1, acc1);
            acc2 = __hfma2(tanh2(__hmul2(ch, h2)), h2, acc2);
            acc3 = __hfma2(tanh2(__hmul2(ch, h3)), h3, acc3);
        }

        // Flush chunk to f32 (only F2F in the hot path: 8 per chunk)
        float2 f0 = __half22float2(acc0);
        float2 f1 = __half22float2(acc1);
        float2 f2 = __half22float2(acc2);
        float2 f3 = __half22float2(acc3);
        facc += ((f0.x + f0.y) + (f1.x + f1.y))
              + ((f2.x + f2.y) + (f3.x + f3.y));
    }

    partial[threadIdx.x] = facc;
    __syncthreads();

    if (threadIdx.x < OUTS) {
        float s = partial[threadIdx.x]
                + partial[threadIdx.x + OUTS]
                + partial[threadIdx.x + 2 * OUTS]
                + partial[threadIdx.x + 3 * OUTS];
        out[batch * NDIM + n] = b[0] * s;
    }
}

extern "C" void kernel_launch(void* const* d_in, const int* in_sizes, int n_in,
                              void* d_out, int out_size)
{
    const float* x = (const float*)d_in[0];
    const float* a = (const float*)d_in[1];
    const float* b = (const float*)d_in[2];
    float* out = (float*)d_out;

    dim3 grid(NDIM / OUTS, NBATCH);   // 64 x 16 = 1024 blocks, 256 threads
    custom_attention_kernel<<<grid, BT>>>(x, a, b, out);
}

// round 4
// speedup vs baseline: 1.7727x; 1.4553x over previous
#include <cuda_runtime.h>
#include <cuda_fp16.h>

// CustomAttention: out[b,n] = b0 * sum_m tanh(a0*x[b,n]*x[b,m]) * x[b,m]
// B=16, N=4096. At the MUFU result-throughput roofline -> halve tanh count
// via symmetry t(n,m)=t(m,n). Tile pairs (I<=J) of 256x256; off-diagonal
// blocks serve both out-rows-I and out-rows-J from one tanh per element.
// Transposed contributions transported lane-to-lane with SHFL (MIO pipe,
// overlaps XU). Deterministic: exclusive-write scratch slots, no atomics.

#define NBATCH 16
#define NDIM   4096
#define TILE   256
#define NTILE  (NDIM / TILE)              // 16
#define NPAIR  (NTILE * (NTILE + 1) / 2)  // 136
#define BT     256

// scratch[batch][slot][row]: each (slot,row-tile) cell written by exactly one block
__device__ float g_scratch[NBATCH][NTILE][NDIM];

__device__ __forceinline__ __half2 tanh2(__half2 v) {
    unsigned u = *reinterpret_cast<unsigned*>(&v);
    unsigned r;
    asm("tanh.approx.f16x2 %0, %1;" : "=r"(r) : "r"(u));
    return *reinterpret_cast<__half2*>(&r);
}
__device__ __forceinline__ unsigned h2u(__half2 v) { return *reinterpret_cast<unsigned*>(&v); }
__device__ __forceinline__ __half2 u2h(unsigned v) { return *reinterpret_cast<__half2*>(&v); }

__global__ __launch_bounds__(BT)
void sym_tile_kernel(const float* __restrict__ x,
                     const float* __restrict__ a)
{
    __shared__ __half2 xhJ[TILE / 2];          // col tile as f16 pairs, 512 B
    __shared__ float2  colred[8][TILE / 2];    // per-warp col partials, 8 KB

    const int batch = blockIdx.y;
    const int tid   = threadIdx.x;
    const int w     = tid >> 5;
    const int L     = tid & 31;

    // Decode linear pair index -> (I, J), I <= J
    int p = blockIdx.x, I = 0;
    while (true) { int cnt = NTILE - I; if (p < cnt) break; p -= cnt; I++; }
    const int J = I + p;

    const float* __restrict__ xb = x + batch * NDIM;

    // Column tile J -> f16 pairs in SMEM
    if (tid < TILE / 2) {
        float2 v = reinterpret_cast<const float2*>(xb + J * TILE)[tid];
        xhJ[tid] = __floats2half2_rn(v.x, v.y);
    }

    // This thread's row (tile I, row tid): scale and f16 weight
    const float xn = xb[I * TILE + tid];
    const __half2 ch  = __float2half2_rn(a[0] * xn);
    const __half2 xi2 = __float2half2_rn(xn);
    __syncthreads();

    float row_f = 0.f;

    if (I == J) {
        // Diagonal: plain row accumulation over the full tile
        #pragma unroll 1
        for (int rb = 0; rb < 4; ++rb) {
            __half2 racc = __float2half2_rn(0.f);
            #pragma unroll
            for (int k = 0; k < 32; ++k) {
                __half2 h = xhJ[rb * 32 + k];
                racc = __hfma2(tanh2(__hmul2(ch, h)), h, racc);
            }
            float2 f = __half22float2(racc);
            row_f += f.x + f.y;
        }
        g_scratch[batch][I][I * TILE + tid] = row_f;
    } else {
        // Off-diagonal: rotating-pair symmetric accumulation.
        // Lane L owns row (I*256 + 32w + L) and col-pair (rb*32 + L) of tile J.
        #pragma unroll 1
        for (int rb = 0; rb < 4; ++rb) {
            __half2 racc = __float2half2_rn(0.f);
            __half2 cacc = __float2half2_rn(0.f);
            #pragma unroll
            for (int k = 0; k < 32; ++k) {
                const int pc = (L + k) & 31;             // col-pair this lane computes
                __half2 h = xhJ[rb * 32 + pc];
                __half2 t = tanh2(__hmul2(ch, h));
                racc = __hfma2(t, h, racc);              // -> out rows of I
                unsigned v2 = h2u(__hmul2(t, xi2));      // t * x_row -> out rows of J
                unsigned rv = __shfl_sync(0xffffffffu, v2, (L - k) & 31);
                cacc = __hadd2(cacc, u2h(rv));           // owner lane accumulates its pair
            }
            float2 f = __half22float2(racc);
            row_f += f.x + f.y;
            colred[w][rb * 32 + L] = __half22float2(cacc);
        }
        __syncthreads();

        // Reduce col partials across the 8 warps: thread tid handles col element tid
        float s = 0.f;
        #pragma unroll
        for (int w2 = 0; w2 < 8; ++w2) {
            float2 f = colred[w2][tid >> 1];
            s += (tid & 1) ? f.y : f.x;
        }
        g_scratch[batch][J][I * TILE + tid] = row_f;   // row side: rows of I, slot J
        g_scratch[batch][I][J * TILE + tid] = s;       // col side: rows of J, slot I
    }
}

__global__ __launch_bounds__(BT)
void reduce_kernel(const float* __restrict__ b, float* __restrict__ out)
{
    const int idx   = blockIdx.x * BT + threadIdx.x;   // 0..65535
    const int batch = idx >> 12;
    const int n     = idx & (NDIM - 1);
    float s = 0.f;
    #pragma unroll
    for (int slot = 0; slot < NTILE; ++slot)
        s += g_scratch[batch][slot][n];
    out[idx] = b[0] * s;
}

extern "C" void kernel_launch(void* const* d_in, const int* in_sizes, int n_in,
                              void* d_out, int out_size)
{
    const float* x = (const float*)d_in[0];
    const float* a = (const float*)d_in[1];
    const float* b = (const float*)d_in[2];
    float* out = (float*)d_out;

    dim3 grid(NPAIR, NBATCH);                       // 136 x 16 = 2176 blocks
    sym_tile_kernel<<<grid, BT>>>(x, a);
    reduce_kernel<<<(NBATCH * NDIM) / BT, BT>>>(b, out);
}

// round 5
// speedup vs baseline: 1.8571x; 1.0476x over previous
#include <cuda_runtime.h>
#include <cuda_fp16.h>

// CustomAttention: out[b,n] = b0 * sum_m tanh(a0*x[b,n]*x[b,m]) * x[b,m]
// B=16, N=4096. Symmetric tiling (R4) + R5: affine LDS addressing via
// replicated column tile (kills per-k mask ALU), wrap-free shfl lanes,
// and a restructured slot-parallel reduce kernel (1024 blocks, 4-deep
// load chains instead of 256 blocks x 16-deep).

#define NBATCH 16
#define NDIM   4096
#define TILE   256
#define NTILE  (NDIM / TILE)              // 16
#define NPAIR  (NTILE * (NTILE + 1) / 2)  // 136
#define BT     256

__device__ float g_scratch[NBATCH][NTILE][NDIM];   // exclusive-write slots

__device__ __forceinline__ __half2 tanh2(__half2 v) {
    unsigned u = *reinterpret_cast<unsigned*>(&v);
    unsigned r;
    asm("tanh.approx.f16x2 %0, %1;" : "=r"(r) : "r"(u));
    return *reinterpret_cast<__half2*>(&r);
}
__device__ __forceinline__ unsigned h2u(__half2 v) { return *reinterpret_cast<unsigned*>(&v); }
__device__ __forceinline__ __half2 u2h(unsigned v) { return *reinterpret_cast<__half2*>(&v); }

__global__ __launch_bounds__(BT)
void sym_tile_kernel(const float* __restrict__ x,
                     const float* __restrict__ a)
{
    // Column tile J as f16 pairs, REPLICATED mod 32 within each rb group:
    // xhJd[rb][j] = pair (rb*32 + (j&31)) -> k-loop index L+k is affine.
    __shared__ __half2 xhJd[4][64];            // 2 KB
    __shared__ float2  colred[8][TILE / 2];    // 8 KB

    const int batch = blockIdx.y;
    const int tid   = threadIdx.x;
    const int w     = tid >> 5;
    const int L     = tid & 31;

    // Decode linear pair index -> (I, J), I <= J
    int p = blockIdx.x, I = 0;
    while (true) { int cnt = NTILE - I; if (p < cnt) break; p -= cnt; I++; }
    const int J = I + p;

    const float* __restrict__ xb = x + batch * NDIM;

    // Fill replicated col tile: 256 threads -> 256 entries (4 rb x 64 j)
    {
        const int rb  = tid >> 6;
        const int j   = tid & 63;
        const int pr  = rb * 32 + (j & 31);    // source pair in tile J
        float2 v = reinterpret_cast<const float2*>(xb + J * TILE)[pr];
        xhJd[rb][j] = __floats2half2_rn(v.x, v.y);
    }

    const float xn = xb[I * TILE + tid];
    const __half2 ch  = __float2half2_rn(a[0] * xn);
    const __half2 xi2 = __float2half2_rn(xn);
    __syncthreads();

    float row_f = 0.f;

    if (I == J) {
        #pragma unroll 1
        for (int rb = 0; rb < 4; ++rb) {
            __half2 racc = __float2half2_rn(0.f);
            #pragma unroll
            for (int k = 0; k < 32; ++k) {
                __half2 h = xhJd[rb][k];
                racc = __hfma2(tanh2(__hmul2(ch, h)), h, racc);
            }
            float2 f = __half22float2(racc);
            row_f += f.x + f.y;
        }
        g_scratch[batch][I][I * TILE + tid] = row_f;
    } else {
        #pragma unroll 1
        for (int rb = 0; rb < 4; ++rb) {
            __half2 racc = __float2half2_rn(0.f);
            __half2 cacc = __float2half2_rn(0.f);
            #pragma unroll
            for (int k = 0; k < 32; ++k) {
                __half2 h = xhJd[rb][L + k];             // affine: imm offset k*4
                __half2 t = tanh2(__hmul2(ch, h));
                racc = __hfma2(t, h, racc);              // rows of I
                unsigned v2 = h2u(__hmul2(t, xi2));      // t * x_row -> rows of J
                unsigned rv = __shfl_sync(0xffffffffu, v2, L + 32 - k); // mod-32 wrap
                cacc = __hadd2(cacc, u2h(rv));
            }
            float2 f = __half22float2(racc);
            row_f += f.x + f.y;
            colred[w][rb * 32 + L] = __half22float2(cacc);
        }
        __syncthreads();

        float s = 0.f;
        #pragma unroll
        for (int w2 = 0; w2 < 8; ++w2) {
            float2 f = colred[w2][tid >> 1];
            s += (tid & 1) ? f.y : f.x;
        }
        g_scratch[batch][J][I * TILE + tid] = row_f;   // rows of I, slot J
        g_scratch[batch][I][J * TILE + tid] = s;       // rows of J, slot I
    }
}

// Slot-parallel reduce: 1024 blocks, each covers 64 outputs x 16 slots.
// Thread (o, g) sums 4 slots; SMEM tree folds the 4 groups.
__global__ __launch_bounds__(BT)
void reduce_kernel(const float* __restrict__ b, float* __restrict__ out)
{
    __shared__ float red[BT];
    const int o     = threadIdx.x & 63;
    const int g     = threadIdx.x >> 6;                 // slot group 0..3
    const int idx   = blockIdx.x * 64 + o;              // global output
    const int batch = idx >> 12;
    const int n     = idx & (NDIM - 1);

    float s = 0.f;
    #pragma unroll
    for (int k = 0; k < 4; ++k)
        s += g_scratch[batch][g * 4 + k][n];
    red[threadIdx.x] = s;
    __syncthreads();

    if (threadIdx.x < 64) {
        float tot = red[threadIdx.x] + red[threadIdx.x + 64]
                  + red[threadIdx.x + 128] + red[threadIdx.x + 192];
        out[idx] = b[0] * tot;
    }
}

extern "C" void kernel_launch(void* const* d_in, const int* in_sizes, int n_in,
                              void* d_out, int out_size)
{
    const float* x = (const float*)d_in[0];
    const float* a = (const float*)d_in[1];
    const float* b = (const float*)d_in[2];
    float* out = (float*)d_out;

    dim3 grid(NPAIR, NBATCH);                          // 136 x 16 = 2176 blocks
    sym_tile_kernel<<<grid, BT>>>(x, a);
    reduce_kernel<<<(NBATCH * NDIM) / 64, BT>>>(b, out);   // 1024 blocks
}

// round 6
// speedup vs baseline: 1.9485x; 1.0492x over previous
#include <cuda_runtime.h>
#include <cuda_fp16.h>

// CustomAttention: out[b,n] = b0 * sum_m tanh(a0*x[b,n]*x[b,m]) * x[b,m]
// B=16, N=4096. Symmetric 256x256 tiling at the MUFU result roofline.
// R6: f16 scratch (halves scratch traffic; partials are uniformly signed,
// error budget holds), diagonal (half-work) blocks scheduled LAST for a
// smooth wave tail, lean 256-block reduce.

#define NBATCH 16
#define NDIM   4096
#define TILE   256
#define NTILE  (NDIM / TILE)              // 16
#define NOFF   (NTILE * (NTILE - 1) / 2)  // 120 off-diagonal pairs
#define NPAIR  (NOFF + NTILE)             // 136 blocks per batch
#define BT     256

__device__ __half g_scratch[NBATCH][NTILE][NDIM];   // 2 MB, exclusive-write

__device__ __forceinline__ __half2 tanh2(__half2 v) {
    unsigned u = *reinterpret_cast<unsigned*>(&v);
    unsigned r;
    asm("tanh.approx.f16x2 %0, %1;" : "=r"(r) : "r"(u));
    return *reinterpret_cast<__half2*>(&r);
}
__device__ __forceinline__ unsigned h2u(__half2 v) { return *reinterpret_cast<unsigned*>(&v); }
__device__ __forceinline__ __half2 u2h(unsigned v) { return *reinterpret_cast<__half2*>(&v); }

__global__ __launch_bounds__(BT)
void sym_tile_kernel(const float* __restrict__ x,
                     const float* __restrict__ a)
{
    // Column tile J as f16 pairs, replicated mod 32 per rb group -> affine LDS idx
    __shared__ __half2 xhJd[4][64];            // 2 KB
    __shared__ float2  colred[8][TILE / 2];    // 8 KB

    const int batch = blockIdx.y;
    const int tid   = threadIdx.x;
    const int w     = tid >> 5;
    const int L     = tid & 31;

    // bid 0..119: off-diagonal pairs I<J; bid 120..135: diagonal (light, last)
    int I, J;
    if (blockIdx.x < NOFF) {
        int q = blockIdx.x, i = 0;
        while (true) { int cnt = NTILE - 1 - i; if (q < cnt) break; q -= cnt; i++; }
        I = i; J = i + 1 + q;
    } else {
        I = J = blockIdx.x - NOFF;
    }

    const float* __restrict__ xb = x + batch * NDIM;

    // Fill replicated col tile: 256 threads -> 4 rb x 64 entries
    {
        const int rb = tid >> 6;
        const int j  = tid & 63;
        const int pr = rb * 32 + (j & 31);
        float2 v = reinterpret_cast<const float2*>(xb + J * TILE)[pr];
        xhJd[rb][j] = __floats2half2_rn(v.x, v.y);
    }

    const float xn = xb[I * TILE + tid];
    const __half2 ch  = __float2half2_rn(a[0] * xn);
    const __half2 xi2 = __float2half2_rn(xn);
    __syncthreads();

    float row_f = 0.f;

    if (I == J) {
        #pragma unroll 1
        for (int rb = 0; rb < 4; ++rb) {
            __half2 racc = __float2half2_rn(0.f);
            #pragma unroll
            for (int k = 0; k < 32; ++k) {
                __half2 h = xhJd[rb][k];
                racc = __hfma2(tanh2(__hmul2(ch, h)), h, racc);
            }
            float2 f = __half22float2(racc);
            row_f += f.x + f.y;
        }
        g_scratch[batch][I][I * TILE + tid] = __float2half(row_f);
    } else {
        #pragma unroll 1
        for (int rb = 0; rb < 4; ++rb) {
            __half2 racc = __float2half2_rn(0.f);
            __half2 cacc = __float2half2_rn(0.f);
            #pragma unroll
            for (int k = 0; k < 32; ++k) {
                __half2 h = xhJd[rb][L + k];             // affine LDS (imm offset)
                __half2 t = tanh2(__hmul2(ch, h));
                racc = __hfma2(t, h, racc);              // rows of I
                unsigned v2 = h2u(__hmul2(t, xi2));      // t * x_row -> rows of J
                unsigned rv = __shfl_sync(0xffffffffu, v2, L + 32 - k);
                cacc = __hadd2(cacc, u2h(rv));
            }
            float2 f = __half22float2(racc);
            row_f += f.x + f.y;
            colred[w][rb * 32 + L] = __half22float2(cacc);
        }
        __syncthreads();

        float s = 0.f;
        #pragma unroll
        for (int w2 = 0; w2 < 8; ++w2) {
            float2 f = colred[w2][tid >> 1];
            s += (tid & 1) ? f.y : f.x;
        }
        g_scratch[batch][J][I * TILE + tid] = __float2half(row_f); // rows I, slot J
        g_scratch[batch][I][J * TILE + tid] = __float2half(s);     // rows J, slot I
    }
}

// 256 blocks x 256 threads, one output per thread, 16 contiguous f16 loads.
__global__ __launch_bounds__(BT)
void reduce_kernel(const float* __restrict__ b, float* __restrict__ out)
{
    const int idx   = blockIdx.x * BT + threadIdx.x;   // 0..65535
    const int batch = idx >> 12;
    const int n     = idx & (NDIM - 1);
    float s = 0.f;
    #pragma unroll
    for (int slot = 0; slot < NTILE; ++slot)
        s += __half2float(g_scratch[batch][slot][n]);
    out[idx] = b[0] * s;
}

extern "C" void kernel_launch(void* const* d_in, const int* in_sizes, int n_in,
                              void* d_out, int out_size)
{
    const float* x = (const float*)d_in[0];
    const float* a = (const float*)d_in[1];
    const float* b = (const float*)d_in[2];
    float* out = (float*)d_out;

    dim3 grid(NPAIR, NBATCH);                       // 136 x 16 = 2176 blocks
    sym_tile_kernel<<<grid, BT>>>(x, a);
    reduce_kernel<<<(NBATCH * NDIM) / BT, BT>>>(b, out);
}